// round 17
// baseline (speedup 1.0000x reference)
#include <cuda_runtime.h>
#include <cstdint>

// out[i] = 0.5 * sum_{bonds b with adj[b,0]==i} par[b] * (|xyz[a0]-xyz[a1]| - len[b])^2
// bond_adj arrives as int32 (JAX x64-disabled downcasts int64).
//
// Measured structural floor: main kernel ~3.1 L1tex wavefronts/bond
// (2 random LDG.128 gathers + 1 RED + streams) at 1 wf/cyc/SM -> ~90us;
// prep (64MB DRAM) ~8us. We sit at ~98% of that floor.
//  - xyz repacked to float4 table (1 sector/1 wavefront per endpoint gather)
//  - prep: 2 atoms/thread, 3x LDG.64 (8B-aligned at 24B stride), fused zeroing
//  - main: 2 bonds/thread (int4 adj), plain __ldg (R11 config, best measured)

#define MAX_ATOMS 2000000
__device__ float4 g_xyz4[MAX_ATOMS];   // 32 MB static scratch

// Prep: thread t handles atoms 2t, 2t+1. Reads 24B via 3 aligned float2 loads
// (base = 24*t, 8B-aligned), writes 2 float4 table entries + float2 zero.
__global__ void __launch_bounds__(256)
prep_kernel_v2(const float2* __restrict__ xyz2,  // xyz viewed as float2[3N/2]
               float2* __restrict__ out2,        // out viewed as float2[N/2]
               int npairs_atoms)                 // natoms/2
{
    int t = blockIdx.x * blockDim.x + threadIdx.x;
    if (t >= npairs_atoms) return;

    float2 u0 = __ldg(xyz2 + 3 * t + 0);   // x0 y0
    float2 u1 = __ldg(xyz2 + 3 * t + 1);   // z0 x1
    float2 u2 = __ldg(xyz2 + 3 * t + 2);   // y1 z1

    int base = 2 * t;
    g_xyz4[base + 0] = make_float4(u0.x, u0.y, u1.x, 0.0f);
    g_xyz4[base + 1] = make_float4(u1.y, u2.x, u2.y, 0.0f);

    out2[t] = make_float2(0.0f, 0.0f);
}

// Scalar prep tail (natoms odd)
__global__ void __launch_bounds__(128)
prep_kernel_tail(const float* __restrict__ xyz, float* __restrict__ out,
                 int start, int natoms)
{
    int i = start + blockIdx.x * blockDim.x + threadIdx.x;
    if (i >= natoms) return;
    out[i] = 0.0f;
    const float* p = xyz + (size_t)i * 3;
    g_xyz4[i] = make_float4(p[0], p[1], p[2], 0.0f);
}

__device__ __forceinline__ float bond_e(float4 a, float4 b, float len, float par)
{
    float dx = a.x - b.x;
    float dy = a.y - b.y;
    float dz = a.z - b.z;
    float d  = sqrtf(fmaf(dx, dx, fmaf(dy, dy, dz * dz)));
    float t  = d - len;
    return 0.5f * par * t * t;
}

// 2 bonds per thread (R11 config: best measured main-kernel time, 91.7us)
__global__ void __launch_bounds__(256, 8)
bond_energy_kernel(const int4*   __restrict__ adj2,  // [E/2]: two pairs per int4
                   const float2* __restrict__ blen2, // [E/2]
                   const float2* __restrict__ bpar2, // [E/2]
                   float* __restrict__ out,          // [N]
                   int npairs)                       // E/2
{
    int p = blockIdx.x * blockDim.x + threadIdx.x;
    if (p >= npairs) return;

    int4   ij  = __ldg(adj2 + p);    // (i0,j0,i1,j1)
    float2 len = __ldg(blen2 + p);
    float2 par = __ldg(bpar2 + p);

    // 4 independent gathers in flight before any FP work
    float4 a0 = __ldg(&g_xyz4[ij.x]);
    float4 b0 = __ldg(&g_xyz4[ij.y]);
    float4 a1 = __ldg(&g_xyz4[ij.z]);
    float4 b1 = __ldg(&g_xyz4[ij.w]);

    atomicAdd(out + ij.x, bond_e(a0, b0, len.x, par.x));
    atomicAdd(out + ij.z, bond_e(a1, b1, len.y, par.y));
}

// Tail for odd bond counts
__global__ void __launch_bounds__(128)
bond_energy_tail_kernel(const int2*  __restrict__ adj,
                        const float* __restrict__ blen,
                        const float* __restrict__ bpar,
                        float* __restrict__ out,
                        int start, int nbonds)
{
    int e = start + blockIdx.x * blockDim.x + threadIdx.x;
    if (e >= nbonds) return;
    int2 ij = __ldg(adj + e);
    float4 a = __ldg(&g_xyz4[ij.x]);
    float4 b = __ldg(&g_xyz4[ij.y]);
    atomicAdd(out + ij.x, bond_e(a, b, __ldg(blen + e), __ldg(bpar + e)));
}

extern "C" void kernel_launch(void* const* d_in, const int* in_sizes, int n_in,
                              void* d_out, int out_size)
{
    const float* xyz  = (const float*)d_in[0];  // [N,3]
    const int2*  adj  = (const int2*)d_in[1];   // [E,2] int32
    const float* blen = (const float*)d_in[2];  // [E,1]
    const float* bpar = (const float*)d_in[3];  // [E,1]
    float*       out  = (float*)d_out;          // [N,1]

    int nbonds = in_sizes[1] / 2;
    int natoms = out_size;

    // ---- prep: zero out + repack xyz to float4 table ----
    int apairs = natoms / 2;
    int atail  = apairs * 2;
    if (apairs > 0) {
        int threads = 256;
        prep_kernel_v2<<<(apairs + threads - 1) / threads, threads>>>(
            (const float2*)xyz, (float2*)out, apairs);
    }
    if (atail < natoms) {
        int threads = 128;
        int n = natoms - atail;
        prep_kernel_tail<<<(n + threads - 1) / threads, threads>>>(
            xyz, out, atail, natoms);
    }

    // ---- main: bond energies + scatter ----
    int npairs = nbonds / 2;
    int btail  = npairs * 2;
    if (npairs > 0) {
        int threads = 256;
        bond_energy_kernel<<<(npairs + threads - 1) / threads, threads>>>(
            (const int4*)adj, (const float2*)blen, (const float2*)bpar, out, npairs);
    }
    if (btail < nbonds) {
        int threads = 128;
        int n = nbonds - btail;
        bond_energy_tail_kernel<<<(n + threads - 1) / threads, threads>>>(
            adj, blen, bpar, out, btail, nbonds);
    }
}